// round 17
// baseline (speedup 1.0000x reference)
#include <cuda_runtime.h>
#include <cuda_bf16.h>
#include <cuda_fp16.h>
#include <mma.h>
#include <cstdint>

using namespace nvcuda;

#define T_   512
#define B_   128
#define D_   512
#define H_   1024
#define G3H  3072

// ---- gi_gemm tiling (proven fp16 single-plane) ----
#define MT   128
#define NT   64
#define KT   32
#define PADA 40
#define PADB 72

// ---- scan: 2 row-groups x 64 col-groups; CTA = [64 rows x 16 cols], fp16 ----
#define NCTA    128
#define RROWS   64
#define SKT     256
#define NCHUNK  (H_ / SKT)                  // 4
#define NRING   3
#define A_LD    264                         // fp16 elems/row (528B, conflict-free)
#define CHUNK_ELEMS (RROWS * A_LD)          // 16896
#define CHUNK_BYTES (CHUNK_ELEMS * 2)       // 33792
#define HGRP_ELEMS (NCHUNK * CHUNK_ELEMS)
#define B_LD    24
#define BHALF_BYTES (H_ * B_LD * 2)         // 49152
#define SM_W    0
#define SM_A    (2 * BHALF_BYTES)           // 98304
#define SM_CTL  (SM_A + NRING * CHUNK_BYTES) // 199680
#define SMEM_TOTAL (SM_CTL + 64)
#define NTHREADS 288

__device__ __align__(256) float  g_Gi[(long long)T_ * B_ * G3H];
// h scratch: [pingpong][rowgroup][chunk][64][264] fp16
__device__ __align__(256) __half g_h[2][2 * HGRP_ELEMS];
__device__ int      g_reset_mode;
// per-chunk ready counters: [pingpong][rowgroup][chunk], 16 writers each
__device__ __align__(16) unsigned g_rdy[2][2][NCHUNK];

// ---------------------------------------------------------------------------
__global__ void init_kernel(const unsigned char* __restrict__ resets) {
    const unsigned int* w = (const unsigned int*)resets;
    bool i32 = true, f32 = true;
    for (int i = 0; i < 16; i++) {
        unsigned int v = w[i];
        if (v != 0u && v != 1u) i32 = false;
        if (v != 0u && v != 0x3F800000u) f32 = false;
    }
    g_reset_mode = i32 ? 1 : (f32 ? 2 : 0);
    for (int rg = 0; rg < 2; rg++)
        for (int kc = 0; kc < NCHUNK; kc++) {
            g_rdy[0][rg][kc] = 16u;   // prep_h counts as first write (16 owners)
            g_rdy[1][rg][kc] = 0u;
        }
}

__device__ __forceinline__ bool get_reset_m(const void* r, int idx, int m) {
    if (m == 1) return ((const int*)r)[idx] != 0;
    if (m == 2) return ((const float*)r)[idx] != 0.0f;
    return ((const unsigned char*)r)[idx] != 0;
}

__device__ __forceinline__ unsigned smem_u32(const void* p) {
    return (unsigned)__cvta_generic_to_shared(p);
}
__device__ __forceinline__ void mbar_init(unsigned a, unsigned c) {
    asm volatile("mbarrier.init.shared.b64 [%0], %1;" :: "r"(a), "r"(c) : "memory");
}
__device__ __forceinline__ void mbar_arrive(unsigned a) {
    asm volatile("mbarrier.arrive.shared.b64 _, [%0];" :: "r"(a) : "memory");
}
__device__ __forceinline__ void mbar_expect_tx(unsigned a, unsigned bytes) {
    asm volatile("mbarrier.arrive.expect_tx.shared.b64 _, [%0], %1;"
                 :: "r"(a), "r"(bytes) : "memory");
}
__device__ __forceinline__ void mbar_wait(unsigned a, unsigned parity) {
    asm volatile(
        "{\n\t.reg .pred P;\n\t"
        "W_%=:\n\t"
        "mbarrier.try_wait.parity.acquire.cta.shared::cta.b64 P, [%0], %1, 0x989680;\n\t"
        "@P bra D_%=;\n\t"
        "bra.uni W_%=;\n\t"
        "D_%=:\n\t}"
        :: "r"(a), "r"(parity) : "memory");
}
__device__ __forceinline__ void bulk_ld(unsigned dst, const void* src,
                                        unsigned bytes, unsigned mbar) {
    asm volatile(
        "cp.async.bulk.shared::cta.global.mbarrier::complete_tx::bytes [%0], [%1], %2, [%3];"
        :: "r"(dst), "l"(src), "r"(bytes), "r"(mbar) : "memory");
}
__device__ __forceinline__ unsigned ld_acquire(const unsigned* p) {
    unsigned v;
    asm volatile("ld.acquire.gpu.u32 %0, [%1];" : "=r"(v) : "l"(p) : "memory");
    return v;
}
__device__ __forceinline__ void fence_release() {
    asm volatile("fence.acq_rel.gpu;" ::: "memory");
}

__device__ __forceinline__ void ldsm_x4(unsigned* r, unsigned a) {
    asm volatile("ldmatrix.sync.aligned.m8n8.x4.shared.b16 {%0,%1,%2,%3}, [%4];"
                 : "=r"(r[0]), "=r"(r[1]), "=r"(r[2]), "=r"(r[3]) : "r"(a));
}
__device__ __forceinline__ void ldsm_x4t(unsigned* r, unsigned a) {
    asm volatile("ldmatrix.sync.aligned.m8n8.x4.trans.shared.b16 {%0,%1,%2,%3}, [%4];"
                 : "=r"(r[0]), "=r"(r[1]), "=r"(r[2]), "=r"(r[3]) : "r"(a));
}
__device__ __forceinline__ void ldsm_x2t(unsigned* r, unsigned a) {
    asm volatile("ldmatrix.sync.aligned.m8n8.x2.trans.shared.b16 {%0,%1}, [%2];"
                 : "=r"(r[0]), "=r"(r[1]) : "r"(a));
}
__device__ __forceinline__ void mma16816h(float* c, const unsigned* a, const unsigned* b) {
    asm volatile(
        "mma.sync.aligned.m16n8k16.row.col.f32.f16.f16.f32 "
        "{%0,%1,%2,%3}, {%4,%5,%6,%7}, {%8,%9}, {%0,%1,%2,%3};"
        : "+f"(c[0]), "+f"(c[1]), "+f"(c[2]), "+f"(c[3])
        : "r"(a[0]), "r"(a[1]), "r"(a[2]), "r"(a[3]), "r"(b[0]), "r"(b[1]));
}

__global__ void prep_h_kernel(const float* __restrict__ h0,
                              const void* __restrict__ resets)
{
    int i = blockIdx.x * 256 + threadIdx.x;    // 0 .. B*H-1
    int b = i >> 10;
    int k = i & 1023;
    float v = get_reset_m(resets, b, g_reset_mode) ? 0.0f : h0[i];
    int rg = b >> 6;
    int r  = b & 63;
    int o = rg * HGRP_ELEMS + (k >> 8) * CHUNK_ELEMS + r * A_LD + (k & 255);
    g_h[0][o] = __float2half_rn(v);
}

// ---------------------------------------------------------------------------
// Phase B: Gi = X @ Wi + bi   (proven, fp16 single-plane, verbatim)
// ---------------------------------------------------------------------------
__global__ __launch_bounds__(256) void gi_gemm_kernel(
    const float* __restrict__ X,
    const float* __restrict__ Wi,
    const float* __restrict__ bi)
{
    __shared__ __align__(16) __half sA[MT * PADA];
    __shared__ __align__(16) __half sB[KT * PADB];
    __shared__ __align__(16) float sBias[16 * NT];

    const int n0  = blockIdx.x * NT;
    const long long m0 = (long long)blockIdx.y * MT;
    const int tid  = threadIdx.x;
    const int warp = tid >> 5;
    const int wm   = warp & 3;
    const int wn   = warp >> 2;

    for (int i = tid; i < 16 * NT; i += 256) sBias[i] = bi[n0 + (i % NT)];
    __syncthreads();

    wmma::fragment<wmma::accumulator, 16, 16, 16, float> acc[2][2];
    for (int i = 0; i < 2; i++)
        for (int j = 0; j < 2; j++)
            wmma::load_matrix_sync(acc[i][j], &sBias[wn * 32 + j * 16], NT,
                                   wmma::mem_row_major);

    for (int k0 = 0; k0 < D_; k0 += KT) {
        __syncthreads();
        for (int i = tid; i < MT * KT / 4; i += 256) {
            int r = i >> 3;
            int c = (i & 7) * 4;
            float4 v = *(const float4*)(X + (m0 + r) * D_ + k0 + c);
            sA[r * PADA + c + 0] = __float2half_rn(v.x);
            sA[r * PADA + c + 1] = __float2half_rn(v.y);
            sA[r * PADA + c + 2] = __float2half_rn(v.z);
            sA[r * PADA + c + 3] = __float2half_rn(v.w);
        }
        for (int i = tid; i < KT * NT / 4; i += 256) {
            int r = i >> 4;
            int c = (i & 15) * 4;
            float4 v = *(const float4*)(Wi + (long long)(k0 + r) * G3H + n0 + c);
            sB[r * PADB + c + 0] = __float2half_rn(v.x);
            sB[r * PADB + c + 1] = __float2half_rn(v.y);
            sB[r * PADB + c + 2] = __float2half_rn(v.z);
            sB[r * PADB + c + 3] = __float2half_rn(v.w);
        }
        __syncthreads();

        #pragma unroll
        for (int kk = 0; kk < KT; kk += 16) {
            wmma::fragment<wmma::matrix_a, 16, 16, 16, __half, wmma::row_major> a[2];
            wmma::fragment<wmma::matrix_b, 16, 16, 16, __half, wmma::row_major> b[2];
            #pragma unroll
            for (int i = 0; i < 2; i++)
                wmma::load_matrix_sync(a[i], &sA[(wm * 32 + i * 16) * PADA + kk], PADA);
            #pragma unroll
            for (int j = 0; j < 2; j++)
                wmma::load_matrix_sync(b[j], &sB[kk * PADB + wn * 32 + j * 16], PADB);
            #pragma unroll
            for (int i = 0; i < 2; i++)
                #pragma unroll
                for (int j = 0; j < 2; j++)
                    wmma::mma_sync(acc[i][j], a[i], b[j], acc[i][j]);
        }
    }

    for (int i = 0; i < 2; i++)
        for (int j = 0; j < 2; j++) {
            float* p = g_Gi + (m0 + wm * 32 + i * 16) * G3H + n0 + wn * 32 + j * 16;
            wmma::store_matrix_sync(p, acc[i][j], G3H, wmma::mem_row_major);
        }
}

// ---------------------------------------------------------------------------
// Persistent scan (fp16x1, SKT=256): 128 CTAs x 288 threads.
// Producer gates each chunk's TMA on a per-chunk ready counter (16 owners):
// early chunks stream while straggler CTAs are still in their epilogues.
// ---------------------------------------------------------------------------
__global__ __launch_bounds__(NTHREADS, 1) void scan_kernel(
    const float* __restrict__ Wh,
    const float* __restrict__ bhn,
    const void*  __restrict__ resets,
    float*       __restrict__ out)
{
    extern __shared__ __align__(128) char sm[];
    __half* sW = (__half*)(sm + SM_W);
    const unsigned sW_u32 = smem_u32(sm + SM_W);
    const unsigned sA_u32 = smem_u32(sm + SM_A);
    const unsigned ctl      = smem_u32(sm + SM_CTL);
    const unsigned mb_full  = ctl;        // 3 x 8B
    const unsigned mb_empty = ctl + 24;   // 3 x 8B

    const int tid = threadIdx.x;
    const int wid = tid >> 5;
    const int lid = tid & 31;
    const int bid = blockIdx.x;
    const int rg  = bid >> 6;
    const int j0  = (bid & 63) * 16;
    const int rmode = g_reset_mode;
    const int mychunk = j0 >> 8;          // chunk containing this CTA's cols

    // ---- load resident Wh slice: 48 packed cols (fp16)
    for (int idx = tid; idx < H_ * 48; idx += NTHREADS) {
        int k = idx / 48;
        int c = idx - k * 48;
        int h = c >= 24;
        int cr = c - h * 24;
        int g  = cr >> 3;
        int cj = cr & 7;
        float v = Wh[(long long)k * G3H + g * H_ + j0 + h * 8 + cj];
        sW[h * (H_ * B_LD) + k * B_LD + cr] = __float2half_rn(v);
    }

    if (tid == 0) {
        #pragma unroll
        for (int i = 0; i < NRING; i++) {
            mbar_init(mb_full + i * 8, 1);
            mbar_init(mb_empty + i * 8, 8);
        }
    }
    __syncthreads();
    if (tid < 8) {
        #pragma unroll
        for (int i = 0; i < NRING; i++) mbar_arrive(mb_empty + i * 8);
    }
    asm volatile("fence.proxy.async;" ::: "memory");
    __syncthreads();

    // consumer geometry (SKT=256: 528B A rows, kk 0..15)
    const int wm = wid & 3;
    const int nh = (wid >> 2) & 1;
    const unsigned a_off = (unsigned)((wm * 16 + (lid & 15)) * 528 + (lid >> 4) * 16);
    const unsigned b_half = (unsigned)(nh * BHALF_BYTES);
    const unsigned b_lane  = (unsigned)((lid & 15) * 48);
    const unsigned b_lane4 = (unsigned)(((lid >> 4) & 1) * 16 + (lid & 15) * 48);

    // epilogue coords
    const int r0l = wm * 16 + (lid >> 2);
    const int r1l = r0l + 8;
    const int grow0 = rg * 64 + r0l;
    const int grow1 = rg * 64 + r1l;
    const int col = j0 + nh * 8 + (lid & 3) * 2;
    const int hb0 = (col >> 8) * CHUNK_ELEMS + r0l * A_LD + (col & 255);
    const int hb1 = (col >> 8) * CHUNK_ELEMS + r1l * A_LD + (col & 255);
    float bj0 = bhn[col], bj1 = bhn[col + 1];

    unsigned ph_empty = 0;
    unsigned ph_full  = 0;

    // ---- pre-loop prefetch (t=0): gi + hp
    float2 gr0, gz0, gn0, gr1, gz1, gn1;
    float2 hpA, hpB;
    if (wid < 8) {
        const float* gp0 = g_Gi + (long long)grow0 * G3H + col;
        const float* gp1 = g_Gi + (long long)grow1 * G3H + col;
        gr0 = __ldcs((const float2*)gp0);
        gz0 = __ldcs((const float2*)(gp0 + H_));
        gn0 = __ldcs((const float2*)(gp0 + 2 * H_));
        gr1 = __ldcs((const float2*)gp1);
        gz1 = __ldcs((const float2*)(gp1 + H_));
        gn1 = __ldcs((const float2*)(gp1 + 2 * H_));
        const __half* h0p = g_h[0] + rg * HGRP_ELEMS;
        unsigned hh0 = *(const unsigned*)(h0p + hb0);
        unsigned hh1 = *(const unsigned*)(h0p + hb1);
        hpA = __half22float2(*reinterpret_cast<__half2*>(&hh0));
        hpB = __half22float2(*reinterpret_cast<__half2*>(&hh1));
    }

    for (int t = 0; t < T_; t++) {
        if (wid == 8) {
            if (lid == 0) {
                // per-chunk gating: counter[t&1][rg][kc] >= 16*(t/2+1)
                const unsigned target = 16u * (unsigned)(t / 2 + 1);
                const unsigned* cnt = &g_rdy[t & 1][rg][0];
                const char* src = (const char*)(g_h[t & 1] + rg * HGRP_ELEMS);
                for (int kc = 0; kc < NCHUNK; kc++) {
                    while (ld_acquire(cnt + kc) < target) { }
                    int buf = kc - (kc / 3) * 3;
                    mbar_wait(mb_empty + buf * 8, (ph_empty >> buf) & 1u);
                    ph_empty ^= 1u << buf;
                    mbar_expect_tx(mb_full + buf * 8, CHUNK_BYTES);
                    bulk_ld(sA_u32 + buf * CHUNK_BYTES,
                            src + (long long)kc * CHUNK_BYTES,
                            CHUNK_BYTES, mb_full + buf * 8);
                }
            }
        } else {
            bool rstA = (t + 1 < T_) ? get_reset_m(resets, (t + 1) * B_ + grow0, rmode) : false;
            bool rstB = (t + 1 < T_) ? get_reset_m(resets, (t + 1) * B_ + grow1, rmode) : false;

            // ---- mainloop: 4 chunks, 6 chains (3 gates x kk parity)
            float acc[6][4];
            #pragma unroll
            for (int i = 0; i < 6; i++)
                #pragma unroll
                for (int q = 0; q < 4; q++) acc[i][q] = 0.0f;

            for (int kc = 0; kc < NCHUNK; kc++) {
                const int buf = kc - (kc / 3) * 3;
                mbar_wait(mb_full + buf * 8, (ph_full >> buf) & 1u);
                ph_full ^= 1u << buf;

                const unsigned aB = sA_u32 + buf * CHUNK_BYTES;
                #pragma unroll
                for (int kk = 0; kk < 16; kk++) {
                    unsigned ah[4];
                    ldsm_x4(ah, aB + a_off + kk * 32);
                    unsigned bbase = sW_u32 + b_half +
                                     (unsigned)(kc * 256 + kk * 16) * 48u;
                    unsigned b01[4], b2[2];
                    ldsm_x4t(b01, bbase + b_lane4);
                    ldsm_x2t(b2,  bbase + 32 + b_lane);
                    mma16816h(acc[0 * 2 + (kk & 1)], ah, b01 + 0);
                    mma16816h(acc[1 * 2 + (kk & 1)], ah, b01 + 2);
                    mma16816h(acc[2 * 2 + (kk & 1)], ah, b2);
                }
                if (lid == 0) mbar_arrive(mb_empty + buf * 8);
            }

            float gh[3][4];
            #pragma unroll
            for (int tn = 0; tn < 3; tn++)
                #pragma unroll
                for (int q = 0; q < 4; q++)
                    gh[tn][q] = acc[tn * 2][q] + acc[tn * 2 + 1][q];

            // ---- epilogue (register-local; hp carried)
            float hA0, hA1, hB0, hB1;
            {
                float r = 1.f / (1.f + __expf(-(gr0.x + gh[0][0])));
                float z = 1.f / (1.f + __expf(-(gz0.x + gh[1][0])));
                float n = tanhf(gn0.x + r * (gh[2][0] + bj0));
                hA0 = (1.f - z) * n + z * hpA.x;
            }
            {
                float r = 1.f / (1.f + __expf(-(gr0.y + gh[0][1])));
                float z = 1.f / (1.f + __expf(-(gz0.y + gh[1][1])));
                float n = tanhf(gn0.y + r * (gh[2][1] + bj1));
                hA1 = (1.f - z) * n + z * hpA.y;
            }
            {
                float r = 1.f / (1.f + __expf(-(gr1.x + gh[0][2])));
                float z = 1.f / (1.f + __expf(-(gz1.x + gh[1][2])));
                float n = tanhf(gn1.x + r * (gh[2][2] + bj0));
                hB0 = (1.f - z) * n + z * hpB.x;
            }
            {
                float r = 1.f / (1.f + __expf(-(gr1.y + gh[0][3])));
                float z = 1.f / (1.f + __expf(-(gz1.y + gh[1][3])));
                float n = tanhf(gn1.y + r * (gh[2][3] + bj1));
                hB1 = (1.f - z) * n + z * hpB.y;
            }

            if (t + 1 < T_) {
                // masked h store FIRST (the chunk-counter release covers this)
                __half* hdst = g_h[(t + 1) & 1] + rg * HGRP_ELEMS;
                float mA0 = rstA ? 0.f : hA0, mA1 = rstA ? 0.f : hA1;
                float mB0 = rstB ? 0.f : hB0, mB1 = rstB ? 0.f : hB1;
                __half2 sv0 = __floats2half2_rn(mA0, mA1);
                __half2 sv1 = __floats2half2_rn(mB0, mB1);
                *(unsigned*)(hdst + hb0) = *reinterpret_cast<unsigned*>(&sv0);
                *(unsigned*)(hdst + hb1) = *reinterpret_cast<unsigned*>(&sv1);
                hpA = __half22float2(sv0);
                hpB = __half22float2(sv1);

                fence_release();
                asm volatile("bar.sync 1, 256;" ::: "memory");
                if (tid == 0) atomicAdd(&g_rdy[(t + 1) & 1][rg][mychunk], 1u);
            }

            // out store + next-step gi prefetch: hidden under the TMA refill
            float* outp = out + (long long)t * B_ * H_;
            *(float2*)(outp + (long long)grow0 * H_ + col) = make_float2(hA0, hA1);
            *(float2*)(outp + (long long)grow1 * H_ + col) = make_float2(hB0, hB1);

            if (t + 1 < T_) {
                const float* gp0 = g_Gi + (long long)(t + 1) * B_ * G3H
                                 + (long long)grow0 * G3H + col;
                const float* gp1 = g_Gi + (long long)(t + 1) * B_ * G3H
                                 + (long long)grow1 * G3H + col;
                gr0 = __ldcs((const float2*)gp0);
                gz0 = __ldcs((const float2*)(gp0 + H_));
                gn0 = __ldcs((const float2*)(gp0 + 2 * H_));
                gr1 = __ldcs((const float2*)gp1);
                gz1 = __ldcs((const float2*)(gp1 + H_));
                gn1 = __ldcs((const float2*)(gp1 + 2 * H_));
            }
        }
    }
}

// ---------------------------------------------------------------------------
extern "C" void kernel_launch(void* const* d_in, const int* in_sizes, int n_in,
                              void* d_out, int out_size)
{
    const float* x      = (const float*)d_in[0];
    const void*  resets = d_in[1];
    const float* h0     = (const float*)d_in[2];
    const float* Wi     = (const float*)d_in[3];
    const float* bi     = (const float*)d_in[4];
    const float* Wh     = (const float*)d_in[5];
    const float* bhn    = (const float*)d_in[6];
    float* out = (float*)d_out;

    cudaFuncSetAttribute(scan_kernel, cudaFuncAttributeMaxDynamicSharedMemorySize,
                         SMEM_TOTAL);

    init_kernel<<<1, 1>>>((const unsigned char*)resets);
    prep_h_kernel<<<(B_ * H_) / 256, 256>>>(h0, resets);
    gi_gemm_kernel<<<dim3(G3H / NT, (T_ * B_) / MT), 256>>>(x, Wi, bi);
    scan_kernel<<<NCTA, NTHREADS, SMEM_TOTAL>>>(Wh, bhn, resets, out);
}